// round 6
// baseline (speedup 1.0000x reference)
#include <cuda_runtime.h>
#include <cstdint>

// EmbeddingBag(mode='sum'), T=26, V=200000, D=64, B=4096, L=20.
// weights [T,V,D] f32, lS_o [T,B] i32, lS_i [T,N] i32 -> out [T,B,D] f32.
//
// Strategy: 16-lane sub-warp per bag, float4 row loads (LDG.128, 2 lines/row).
// Cross-replay L2 retention: rows with per-table index < PIN_V are loaded with
// L2::evict_last (sticky ~80MB resident set -> L2 hits on every graph replay
// after the first). Output stores use evict_first to avoid polluting L2.

#define T_TABLES 26
#define V_VOCAB  200000
#define D_DIM    64
#define B_BATCH  4096
#define N_IDX    (4096 * 20)
#define PIN_V    12000     // 26 * 12000 * 256B = 79.9 MB pinned subset (L2 = 126 MB)

__global__ __launch_bounds__(256)
void embbag_kernel(const float* __restrict__ W,
                   const int*   __restrict__ offs,
                   const int*   __restrict__ idx,
                   float*       __restrict__ out)
{
    const int sub   = threadIdx.x >> 4;                 // 16 sub-warps / block
    const int lane4 = threadIdx.x & 15;
    const int bag   = blockIdx.x * 16 + sub;
    if (bag >= T_TABLES * B_BATCH) return;

    const int t = bag / B_BATCH;
    const int b = bag - t * B_BATCH;

    const int start = __ldg(offs + t * B_BATCH + b);
    const int end   = (b + 1 < B_BATCH) ? __ldg(offs + t * B_BATCH + b + 1) : N_IDX;

    const int* __restrict__ idx_t = idx + (size_t)t * N_IDX;
    const float4* __restrict__ Wt =
        reinterpret_cast<const float4*>(W + (size_t)t * V_VOCAB * D_DIM);

    // L2 eviction policies
    uint64_t pol_last, pol_norm, pol_first;
    asm("createpolicy.fractional.L2::evict_last.b64 %0, 1.0;"   : "=l"(pol_last));
    asm("createpolicy.fractional.L2::evict_normal.b64 %0, 1.0;" : "=l"(pol_norm));
    asm("createpolicy.fractional.L2::evict_first.b64 %0, 1.0;"  : "=l"(pol_first));

    float4 acc = make_float4(0.f, 0.f, 0.f, 0.f);

    auto load_row = [&](int r) -> float4 {
        const float4* p = Wt + (size_t)r * 16 + lane4;
        const uint64_t pol = (r < PIN_V) ? pol_last : pol_norm;
        float4 v;
        asm volatile("ld.global.nc.L2::cache_hint.v4.f32 {%0,%1,%2,%3}, [%4], %5;"
                     : "=f"(v.x), "=f"(v.y), "=f"(v.z), "=f"(v.w)
                     : "l"(p), "l"(pol));
        return v;
    };

    int j = start;
    // Unroll x5: 5 independent row-gathers per sub-warp in flight.
    for (; j + 5 <= end; j += 5) {
        const int r0 = __ldg(idx_t + j + 0);
        const int r1 = __ldg(idx_t + j + 1);
        const int r2 = __ldg(idx_t + j + 2);
        const int r3 = __ldg(idx_t + j + 3);
        const int r4 = __ldg(idx_t + j + 4);
        const float4 v0 = load_row(r0);
        const float4 v1 = load_row(r1);
        const float4 v2 = load_row(r2);
        const float4 v3 = load_row(r3);
        const float4 v4 = load_row(r4);
        acc.x += v0.x; acc.y += v0.y; acc.z += v0.z; acc.w += v0.w;
        acc.x += v1.x; acc.y += v1.y; acc.z += v1.z; acc.w += v1.w;
        acc.x += v2.x; acc.y += v2.y; acc.z += v2.z; acc.w += v2.w;
        acc.x += v3.x; acc.y += v3.y; acc.z += v3.z; acc.w += v3.w;
        acc.x += v4.x; acc.y += v4.y; acc.z += v4.z; acc.w += v4.w;
    }
    for (; j < end; ++j) {
        const float4 v = load_row(__ldg(idx_t + j));
        acc.x += v.x; acc.y += v.y; acc.z += v.z; acc.w += v.w;
    }

    // Output: written once, never read back — keep it out of L2's way.
    float4* po = reinterpret_cast<float4*>(out) + (size_t)bag * 16 + lane4;
    asm volatile("st.global.L2::cache_hint.v4.f32 [%0], {%1,%2,%3,%4}, %5;"
                 :: "l"(po), "f"(acc.x), "f"(acc.y), "f"(acc.z), "f"(acc.w),
                    "l"(pol_first)
                 : "memory");
}

extern "C" void kernel_launch(void* const* d_in, const int* in_sizes, int n_in,
                              void* d_out, int out_size)
{
    const float* weights = (const float*)d_in[0];
    const int*   lS_o    = (const int*)  d_in[1];
    const int*   lS_i    = (const int*)  d_in[2];
    float*       out     = (float*)d_out;

    const int total_bags = T_TABLES * B_BATCH;            // 106496
    const int blocks = (total_bags + 15) / 16;            // 6656

    embbag_kernel<<<blocks, 256>>>(weights, lS_o, lS_i, out);
}

// round 8
// speedup vs baseline: 1.0814x; 1.0814x over previous
#include <cuda_runtime.h>
#include <cuda.h>
#include <cstdint>

// EmbeddingBag(mode='sum'), T=26, V=200000, D=64, B=4096, L=20.
// weights [T,V,D] f32 viewed as 2D [T*V, 64] for TMA tile::gather4.
// One bag per warp; 8 warps/CTA; 5 gather4/bag issued from lanes 0..4 in parallel.

#define T_TABLES 26
#define V_VOCAB  200000
#define D_DIM    64
#define B_BATCH  4096
#define L_BAG    20
#define N_IDX    (B_BATCH * L_BAG)

#define WARPS_PER_CTA 8
#define THREADS_TMA   (WARPS_PER_CTA * 32)
#define BAG_BYTES     (L_BAG * D_DIM * 4)   // 5120

__device__ __forceinline__ uint32_t smem_u32(const void* p) {
    uint32_t a;
    asm("{ .reg .u64 t; cvta.to.shared.u64 t, %1; cvt.u32.u64 %0, t; }" : "=r"(a) : "l"(p));
    return a;
}

#define MBARRIER_INIT(addr, cnt) \
    asm volatile("mbarrier.init.shared.b64 [%0], %1;" :: "r"(addr), "r"((uint32_t)(cnt)) : "memory")

#define MBARRIER_EXPECT_TX(addr, bytes) \
    asm volatile("mbarrier.arrive.expect_tx.shared.b64 _, [%0], %1;" \
                 :: "r"(addr), "r"((uint32_t)(bytes)) : "memory")

#define FENCE_PROXY_ASYNC() asm volatile("fence.proxy.async.shared::cta;" ::: "memory")

#define MBARRIER_WAIT_PARITY(mbar_addr, parity) do {                                   \
    uint32_t _m = (mbar_addr); uint32_t _p = (parity); uint32_t _d;                    \
    asm volatile("{\n\t.reg .pred p;\n\t"                                              \
        "mbarrier.try_wait.parity.acquire.cta.shared::cta.b64 p, [%1], %2;\n\t"        \
        "selp.b32 %0, 1, 0, p;\n\t}" : "=r"(_d) : "r"(_m), "r"(_p) : "memory");        \
    if (!_d) {                                                                         \
        asm volatile("{\n\t.reg .pred P1;\n\t"                                         \
            "WL_%=:\n\t"                                                               \
            "mbarrier.try_wait.parity.acquire.cta.shared::cta.b64 P1, [%0], %1, 0x989680;\n\t" \
            "@P1 bra.uni WD_%=;\n\t"                                                   \
            "bra.uni WL_%=;\n\t"                                                       \
            "WD_%=:\n\t}" :: "r"(_m), "r"(_p) : "memory");                             \
    }                                                                                  \
} while (0)

__device__ __forceinline__ void tma_gather4(
    uint32_t dst_smem, const CUtensorMap* tmap,
    int col, int r0, int r1, int r2, int r3, uint32_t mbar)
{
    asm volatile(
        "cp.async.bulk.tensor.2d.shared::cta.global.tile::gather4.mbarrier::complete_tx::bytes "
        "[%0], [%1, {%2, %3, %4, %5, %6}], [%7];"
        :: "r"(dst_smem), "l"(tmap), "r"(col), "r"(r0), "r"(r1), "r"(r2), "r"(r3), "r"(mbar)
        : "memory");
}

__global__ __launch_bounds__(THREADS_TMA)
void embbag_tma_kernel(const __grid_constant__ CUtensorMap tmap,
                       const int* __restrict__ offs,
                       const int* __restrict__ idx,
                       float*     __restrict__ out)
{
    __shared__ alignas(1024) float buf[WARPS_PER_CTA][L_BAG * D_DIM];   // 40 KB
    __shared__ alignas(8) unsigned long long mb[WARPS_PER_CTA];

    const int wid  = threadIdx.x >> 5;        // warp owns one bag
    const int lane = threadIdx.x & 31;
    const int bag  = blockIdx.x * WARPS_PER_CTA + wid;

    const int t = bag / B_BATCH;
    const int b = bag - t * B_BATCH;

    // Init this warp's mbarrier and make it visible to the async proxy.
    const uint32_t mbar = smem_u32(&mb[wid]);
    if (lane == 0) {
        MBARRIER_INIT(mbar, 1);
        FENCE_PROXY_ASYNC();
    }
    __syncwarp();

    // Fetch this warp's 20 indices (lane j holds row j).
    const int start = __ldg(offs + t * B_BATCH + b);
    int myrow = 0;
    if (lane < L_BAG)
        myrow = t * V_VOCAB + __ldg(idx + (size_t)t * N_IDX + start + lane);

    // Distribute quads: lane g (g<5) gathers rows 4g..4g+3.
    const int r0 = __shfl_sync(0xffffffffu, myrow, (lane << 2) + 0);
    const int r1 = __shfl_sync(0xffffffffu, myrow, (lane << 2) + 1);
    const int r2 = __shfl_sync(0xffffffffu, myrow, (lane << 2) + 2);
    const int r3 = __shfl_sync(0xffffffffu, myrow, (lane << 2) + 3);

    if (lane == 0) MBARRIER_EXPECT_TX(mbar, BAG_BYTES);
    __syncwarp();

    if (lane < 5) {
        tma_gather4(smem_u32(&buf[wid][lane * 4 * D_DIM]), &tmap,
                    0, r0, r1, r2, r3, mbar);
    }

    MBARRIER_WAIT_PARITY(mbar, 0);

    // Reduce 20 rows; lane holds float2 column. Row r at p[r*32].
    const float2* p = reinterpret_cast<const float2*>(buf[wid]) + lane;
    float2 acc = make_float2(0.f, 0.f);
    #pragma unroll
    for (int r = 0; r < L_BAG; ++r) {
        const float2 v = p[r * 32];
        acc.x += v.x; acc.y += v.y;
    }

    // Streaming store: don't let the output displace weight lines in L2.
    __stcs(reinterpret_cast<float2*>(out) + (size_t)bag * 32 + lane, acc);
}

// ---------- fallback LDG kernel ----------
__global__ __launch_bounds__(256)
void embbag_ldg_kernel(const float* __restrict__ W,
                       const int*   __restrict__ offs,
                       const int*   __restrict__ idx,
                       float*       __restrict__ out)
{
    const int sub   = threadIdx.x >> 4;
    const int lane4 = threadIdx.x & 15;
    const int bag   = blockIdx.x * 16 + sub;
    if (bag >= T_TABLES * B_BATCH) return;

    const int t = bag / B_BATCH;
    const int b = bag - t * B_BATCH;
    const int start = __ldg(offs + t * B_BATCH + b);
    const int end   = (b + 1 < B_BATCH) ? __ldg(offs + t * B_BATCH + b + 1) : N_IDX;

    const int* __restrict__ idx_t = idx + (size_t)t * N_IDX;
    const float4* __restrict__ Wt =
        reinterpret_cast<const float4*>(W + (size_t)t * V_VOCAB * D_DIM);

    float4 acc = make_float4(0.f, 0.f, 0.f, 0.f);
    int j = start;
    for (; j + 5 <= end; j += 5) {
        const int r0 = __ldg(idx_t + j + 0);
        const int r1 = __ldg(idx_t + j + 1);
        const int r2 = __ldg(idx_t + j + 2);
        const int r3 = __ldg(idx_t + j + 3);
        const int r4 = __ldg(idx_t + j + 4);
        const float4 v0 = __ldg(Wt + (size_t)r0 * 16 + lane4);
        const float4 v1 = __ldg(Wt + (size_t)r1 * 16 + lane4);
        const float4 v2 = __ldg(Wt + (size_t)r2 * 16 + lane4);
        const float4 v3 = __ldg(Wt + (size_t)r3 * 16 + lane4);
        const float4 v4 = __ldg(Wt + (size_t)r4 * 16 + lane4);
        acc.x += v0.x; acc.y += v0.y; acc.z += v0.z; acc.w += v0.w;
        acc.x += v1.x; acc.y += v1.y; acc.z += v1.z; acc.w += v1.w;
        acc.x += v2.x; acc.y += v2.y; acc.z += v2.z; acc.w += v2.w;
        acc.x += v3.x; acc.y += v3.y; acc.z += v3.z; acc.w += v3.w;
        acc.x += v4.x; acc.y += v4.y; acc.z += v4.z; acc.w += v4.w;
    }
    for (; j < end; ++j) {
        const int r = __ldg(idx_t + j);
        const float4 v = __ldg(Wt + (size_t)r * 16 + lane4);
        acc.x += v.x; acc.y += v.y; acc.z += v.z; acc.w += v.w;
    }
    reinterpret_cast<float4*>(out)[(size_t)bag * 16 + lane4] = acc;
}

// ---------- host ----------
typedef CUresult (*EncodeTiledFn)(
    CUtensorMap*, CUtensorMapDataType, cuuint32_t, void*,
    const cuuint64_t*, const cuuint64_t*, const cuuint32_t*, const cuuint32_t*,
    CUtensorMapInterleave, CUtensorMapSwizzle, CUtensorMapL2promotion, CUtensorMapFloatOOBfill);

extern "C" void kernel_launch(void* const* d_in, const int* in_sizes, int n_in,
                              void* d_out, int out_size)
{
    const float* weights = (const float*)d_in[0];
    const int*   lS_o    = (const int*)  d_in[1];
    const int*   lS_i    = (const int*)  d_in[2];
    float*       out     = (float*)d_out;

    bool use_tma = false;
    CUtensorMap tmap;

    void* fp = nullptr;
    cudaDriverEntryPointQueryResult qr = cudaDriverEntryPointSymbolNotFound;
    cudaError_t e = cudaGetDriverEntryPointByVersion(
        "cuTensorMapEncodeTiled", &fp, 12000, cudaEnableDefault, &qr);
    if (e == cudaSuccess && fp != nullptr && qr == cudaDriverEntryPointSuccess) {
        EncodeTiledFn enc = (EncodeTiledFn)fp;
        cuuint64_t dims[2]    = {D_DIM, (cuuint64_t)T_TABLES * V_VOCAB};
        cuuint64_t strides[1] = {D_DIM * sizeof(float)};      // 256 B row stride
        cuuint32_t box[2]     = {D_DIM, 1};
        cuuint32_t estr[2]    = {1, 1};
        CUresult r = enc(&tmap, CU_TENSOR_MAP_DATA_TYPE_FLOAT32, 2, (void*)weights,
                         dims, strides, box, estr,
                         CU_TENSOR_MAP_INTERLEAVE_NONE, CU_TENSOR_MAP_SWIZZLE_NONE,
                         CU_TENSOR_MAP_L2_PROMOTION_L2_256B,
                         CU_TENSOR_MAP_FLOAT_OOB_FILL_NONE);
        if (r == CUDA_SUCCESS) use_tma = true;
    }

    const int total_bags = T_TABLES * B_BATCH;  // 106496

    if (use_tma) {
        const int blocks = total_bags / WARPS_PER_CTA;   // 13312
        embbag_tma_kernel<<<blocks, THREADS_TMA>>>(tmap, lS_o, lS_i, out);
    } else {
        const int blocks = (total_bags + 15) / 16;
        embbag_ldg_kernel<<<blocks, 256>>>(weights, lS_o, lS_i, out);
    }
}